// round 5
// baseline (speedup 1.0000x reference)
#include <cuda_runtime.h>
#include <cuda_fp16.h>
#include <math.h>

// Problem constants (fixed by the reference setup)
#define BATCH    8192
#define FPP      32
#define FT_OUT   1024
#define N_FEAT   49152
#define N_VFEAT  768
#define TOTAL    ((size_t)N_FEAT * FT_OUT)      // 50,331,648 elements

// Combined fp16 weight table: W_comb[r][c] = W_ft[r][c] + W_fft[r % 768][c]
// Stored as uint4 (8 halves). 100.6 MB — fits L2.
__device__ uint4 g_wcomb4[TOTAL / 8];

static __device__ __forceinline__ unsigned h2_as_u32(__half2 h) {
    return *reinterpret_cast<unsigned*>(&h);
}
static __device__ __forceinline__ __half2 u32_as_h2(unsigned u) {
    return *reinterpret_cast<__half2*>(&u);
}

// ---------------------------------------------------------------------------
// Kernel 1: build the combined fp16 table. Streaming reads use __ldcs so the
// f32 source tables do NOT evict the combined table we are writing into L2.
// ---------------------------------------------------------------------------
__global__ __launch_bounds__(256)
void nnue_precompute_kernel(const float* __restrict__ W_ft,
                            const float* __restrict__ W_fft)
{
    const size_t t = (size_t)blockIdx.x * blockDim.x + threadIdx.x; // one uint4 (8 elems)
    if (t >= TOTAL / 8) return;
    const size_t base = t * 8;
    const int row = (int)(base >> 10);          // /1024
    const int col = (int)(base & 1023);

    const float4* a = (const float4*)(W_ft  + ((size_t)row << 10) + col);
    const float4* c = (const float4*)(W_fft + ((size_t)(row % N_VFEAT) << 10) + col);
    const float4 a0 = __ldcs(a);        // streaming: evict-first, keep L2 for table
    const float4 a1 = __ldcs(a + 1);
    const float4 c0 = __ldg(c);         // W_fft is tiny (3 MB), reused 64x — cache it
    const float4 c1 = __ldg(c + 1);

    uint4 o;
    o.x = h2_as_u32(__floats2half2_rn(a0.x + c0.x, a0.y + c0.y));
    o.y = h2_as_u32(__floats2half2_rn(a0.z + c0.z, a0.w + c0.w));
    o.z = h2_as_u32(__floats2half2_rn(a1.x + c1.x, a1.y + c1.y));
    o.w = h2_as_u32(__floats2half2_rn(a1.z + c1.z, a1.w + c1.w));
    g_wcomb4[t] = o;
}

// ---------------------------------------------------------------------------
// Kernel 2: gather + clamp + output dot + sigmoid. One CTA per batch row.
// 128 threads, 8 columns each. __launch_bounds__(128, 16) forces <=32 regs
// so 16 CTAs/SM => 100% occupancy. bias/W_out loads are deferred to the
// per-side epilogue so they are not live across the hot loop.
// ---------------------------------------------------------------------------
__global__ __launch_bounds__(128, 16)
void nnue_gather_kernel(const float* __restrict__ values,
                        const int*   __restrict__ stm_feat,
                        const int*   __restrict__ nstm_feat,
                        const float* __restrict__ b_ft,
                        const float* __restrict__ b_fft,
                        const float* __restrict__ W_out,
                        const float* __restrict__ b_out,
                        float*       __restrict__ out)
{
    const int b   = blockIdx.x;
    const int tid = threadIdx.x;              // 0..127

    __shared__ int   s_idx[2][FPP];
    __shared__ float s_val[FPP];
    __shared__ float s_red[4];                // 4 warps

    const int base = b * FPP;
    if (tid < FPP) {
        s_idx[0][tid] = stm_feat[base + tid];
        s_val[tid]    = values[base + tid];
    } else if (tid < 2 * FPP) {
        s_idx[1][tid - FPP] = nstm_feat[base + tid - FPP];
    }
    __syncthreads();

    const int col = tid * 8;                  // first of 8 columns owned by this thread
    const uint4* tab = g_wcomb4 + tid;        // column offset folded into base pointer

    float partial = 0.0f;

    #pragma unroll
    for (int side = 0; side < 2; ++side) {
        float acc[8];
        #pragma unroll
        for (int i = 0; i < 8; ++i) acc[i] = 0.f;

        #pragma unroll 4
        for (int f = 0; f < FPP; ++f) {
            const int   idx = s_idx[side][f];
            const float v   = s_val[f];
            const uint4 u = __ldg(tab + (size_t)idx * (FT_OUT / 8));
            const float2 p0 = __half22float2(u32_as_h2(u.x));
            const float2 p1 = __half22float2(u32_as_h2(u.y));
            const float2 p2 = __half22float2(u32_as_h2(u.z));
            const float2 p3 = __half22float2(u32_as_h2(u.w));
            acc[0] = fmaf(v, p0.x, acc[0]); acc[1] = fmaf(v, p0.y, acc[1]);
            acc[2] = fmaf(v, p1.x, acc[2]); acc[3] = fmaf(v, p1.y, acc[3]);
            acc[4] = fmaf(v, p2.x, acc[4]); acc[5] = fmaf(v, p2.y, acc[5]);
            acc[6] = fmaf(v, p3.x, acc[6]); acc[7] = fmaf(v, p3.y, acc[7]);
        }

        // Epilogue (loads deferred here to keep hot-loop register count low):
        // h = clamp(acc + b_ft + b_fft, 0, 1);  partial += h . W_out[side half]
        const float4 f0 = __ldg((const float4*)(b_ft  + col));
        const float4 f1 = __ldg((const float4*)(b_ft  + col) + 1);
        const float4 g0 = __ldg((const float4*)(b_fft + col));
        const float4 g1 = __ldg((const float4*)(b_fft + col) + 1);
        const float4 w0 = __ldg((const float4*)(W_out + side * FT_OUT + col));
        const float4 w1 = __ldg((const float4*)(W_out + side * FT_OUT + col) + 1);

        const float bs[8] = { f0.x + g0.x, f0.y + g0.y, f0.z + g0.z, f0.w + g0.w,
                              f1.x + g1.x, f1.y + g1.y, f1.z + g1.z, f1.w + g1.w };
        const float wv[8] = { w0.x, w0.y, w0.z, w0.w, w1.x, w1.y, w1.z, w1.w };
        #pragma unroll
        for (int i = 0; i < 8; ++i) {
            const float h = fminf(fmaxf(acc[i] + bs[i], 0.f), 1.f);
            partial = fmaf(h, wv[i], partial);
        }
    }

    // 128 -> 1 reduction
    #pragma unroll
    for (int off = 16; off > 0; off >>= 1)
        partial += __shfl_down_sync(0xffffffffu, partial, off);
    if ((tid & 31) == 0) s_red[tid >> 5] = partial;
    __syncthreads();

    if (tid == 0) {
        const float x = s_red[0] + s_red[1] + s_red[2] + s_red[3] + __ldg(b_out);
        out[b] = 1.0f / (1.0f + expf(-x));
    }
}

extern "C" void kernel_launch(void* const* d_in, const int* in_sizes, int n_in,
                              void* d_out, int out_size)
{
    // metadata order: values, stm_feat, nstm_feat, batch_idx,
    //                 W_ft, b_ft, W_fft, b_fft, W_out, b_out, size
    const float* values    = (const float*)d_in[0];
    const int*   stm_feat  = (const int*)  d_in[1];
    const int*   nstm_feat = (const int*)  d_in[2];
    const float* W_ft      = (const float*)d_in[4];
    const float* b_ft      = (const float*)d_in[5];
    const float* W_fft     = (const float*)d_in[6];
    const float* b_fft     = (const float*)d_in[7];
    const float* W_out     = (const float*)d_in[8];
    const float* b_out     = (const float*)d_in[9];
    float*       out       = (float*)d_out;

    const int pre_threads = 256;
    const int pre_blocks  = (int)((TOTAL / 8 + pre_threads - 1) / pre_threads);
    nnue_precompute_kernel<<<pre_blocks, pre_threads>>>(W_ft, W_fft);
    nnue_gather_kernel<<<BATCH, 128>>>(values, stm_feat, nstm_feat,
                                       b_ft, b_fft, W_out, b_out, out);
}

// round 8
// speedup vs baseline: 1.2642x; 1.2642x over previous
#include <cuda_runtime.h>
#include <cuda_fp16.h>
#include <math.h>

// Problem constants (fixed by the reference setup)
#define BATCH    8192
#define FPP      32
#define FT_OUT   1024
#define N_FEAT   49152
#define N_VFEAT  768
#define TOTAL    ((size_t)N_FEAT * FT_OUT)      // 50,331,648 elements

// int8 combined table: byte = round(127 * (W_ft[r][c]+W_fft[r%768][c]) / absmax_r) + 128
// 50.3 MB -> comfortably L2-resident. Per-row dequant scale in g_scale.
__device__ unsigned g_wq4[TOTAL / 4];           // 4 bytes per uint, coalesced
__device__ float    g_scale[N_FEAT];

static __device__ __forceinline__ unsigned h2_as_u32(__half2 h) {
    return *reinterpret_cast<unsigned*>(&h);
}
static __device__ __forceinline__ __half2 u32_as_h2(unsigned u) {
    return *reinterpret_cast<__half2*>(&u);
}

// ---------------------------------------------------------------------------
// Kernel 1: build int8 table. One CTA per feature row (256 thr x 1 float4).
// Reads W_ft streaming (__ldcs), W_fft cached (3MB, 64x reuse).
// ---------------------------------------------------------------------------
__global__ __launch_bounds__(256)
void nnue_quant_kernel(const float* __restrict__ W_ft,
                       const float* __restrict__ W_fft)
{
    const int row = blockIdx.x;
    const int tid = threadIdx.x;                 // 0..255, 4 cols each

    const float4 a = __ldcs((const float4*)(W_ft  + (size_t)row * FT_OUT) + tid);
    const float4 c = __ldg ((const float4*)(W_fft + (size_t)(row % N_VFEAT) * FT_OUT) + tid);
    const float w0 = a.x + c.x, w1 = a.y + c.y, w2 = a.z + c.z, w3 = a.w + c.w;

    // absmax over the row
    float m = fmaxf(fmaxf(fabsf(w0), fabsf(w1)), fmaxf(fabsf(w2), fabsf(w3)));
    #pragma unroll
    for (int off = 16; off > 0; off >>= 1)
        m = fmaxf(m, __shfl_xor_sync(0xffffffffu, m, off));
    __shared__ float sm[8];
    if ((tid & 31) == 0) sm[tid >> 5] = m;
    __syncthreads();
    float mm = sm[0];
    #pragma unroll
    for (int i = 1; i < 8; ++i) mm = fmaxf(mm, sm[i]);

    const float inv = (mm > 0.f) ? (127.0f / mm) : 0.f;
    // |w*inv| <= 127 exactly, so round-to-nearest stays in [-127,127]
    const int q0 = __float2int_rn(w0 * inv) + 128;
    const int q1 = __float2int_rn(w1 * inv) + 128;
    const int q2 = __float2int_rn(w2 * inv) + 128;
    const int q3 = __float2int_rn(w3 * inv) + 128;
    g_wq4[(size_t)row * (FT_OUT / 4) + tid] =
        (unsigned)q0 | ((unsigned)q1 << 8) | ((unsigned)q2 << 16) | ((unsigned)q3 << 24);

    if (tid == 0) g_scale[row] = mm * (1.0f / 127.0f);
}

// ---------------------------------------------------------------------------
// Kernel 2: gather (int8, 8 cols/thread via uint2) + clamp + dot + sigmoid.
// Dequant trick: bytes are q+128; PRMT under exponent 0x64 builds half
// 1152+q exactly; HSUB2(., 1152) recovers q; HFMA2 with vs = v*scale.
// ---------------------------------------------------------------------------
__global__ __launch_bounds__(128)
void nnue_gather_kernel(const float* __restrict__ values,
                        const int*   __restrict__ stm_feat,
                        const int*   __restrict__ nstm_feat,
                        const float* __restrict__ b_ft,
                        const float* __restrict__ b_fft,
                        const float* __restrict__ W_out,
                        const float* __restrict__ b_out,
                        float*       __restrict__ out)
{
    const int b   = blockIdx.x;
    const int tid = threadIdx.x;              // 0..127

    __shared__ int      s_idx[2][FPP];
    __shared__ unsigned s_vs [2][FPP];        // half2(v*scale, v*scale)
    __shared__ float    s_red[4];

    const int base = b * FPP;
    if (tid < FPP) {
        const int idx = stm_feat[base + tid];
        s_idx[0][tid] = idx;
        const float vs = values[base + tid] * __ldg(&g_scale[idx]);
        s_vs[0][tid] = h2_as_u32(__float2half2_rn(vs));
    } else if (tid < 2 * FPP) {
        const int t = tid - FPP;
        const int idx = nstm_feat[base + t];
        s_idx[1][t] = idx;
        const float vs = values[base + t] * __ldg(&g_scale[idx]);
        s_vs[1][t] = h2_as_u32(__float2half2_rn(vs));
    }
    __syncthreads();

    const int col = tid * 8;                  // first of 8 owned columns
    const uint2* tab = (const uint2*)g_wq4 + tid;   // + row*128 per feature
    const __half2 magic = u32_as_h2(0x64806480u);   // 1152 in both lanes

    float partial = 0.0f;

    #pragma unroll
    for (int side = 0; side < 2; ++side) {
        __half2 acc0 = u32_as_h2(0u), acc1 = u32_as_h2(0u);
        __half2 acc2 = u32_as_h2(0u), acc3 = u32_as_h2(0u);

        #pragma unroll 4
        for (int f = 0; f < FPP; ++f) {
            const int     idx = s_idx[side][f];
            const __half2 vs  = u32_as_h2(s_vs[side][f]);
            const uint2 u = __ldg(tab + (size_t)idx * (FT_OUT / 8));
            // bytes b0..b3 in u.x, b4..b7 in u.y; build (1152+q) halves
            const __half2 h0 = u32_as_h2(__byte_perm(u.x, 0x64646464u, 0x4140));
            const __half2 h1 = u32_as_h2(__byte_perm(u.x, 0x64646464u, 0x4342));
            const __half2 h2 = u32_as_h2(__byte_perm(u.y, 0x64646464u, 0x4140));
            const __half2 h3 = u32_as_h2(__byte_perm(u.y, 0x64646464u, 0x4342));
            acc0 = __hfma2(vs, __hsub2(h0, magic), acc0);
            acc1 = __hfma2(vs, __hsub2(h1, magic), acc1);
            acc2 = __hfma2(vs, __hsub2(h2, magic), acc2);
            acc3 = __hfma2(vs, __hsub2(h3, magic), acc3);
        }

        const float2 A0 = __half22float2(acc0);
        const float2 A1 = __half22float2(acc1);
        const float2 A2 = __half22float2(acc2);
        const float2 A3 = __half22float2(acc3);
        const float accf[8] = { A0.x, A0.y, A1.x, A1.y, A2.x, A2.y, A3.x, A3.y };

        // Epilogue: h = clamp(acc + b_ft + b_fft, 0, 1); partial += h . W_out
        const float4 f0 = __ldg((const float4*)(b_ft  + col));
        const float4 f1 = __ldg((const float4*)(b_ft  + col) + 1);
        const float4 g0 = __ldg((const float4*)(b_fft + col));
        const float4 g1 = __ldg((const float4*)(b_fft + col) + 1);
        const float4 w0 = __ldg((const float4*)(W_out + side * FT_OUT + col));
        const float4 w1 = __ldg((const float4*)(W_out + side * FT_OUT + col) + 1);

        const float bs[8] = { f0.x + g0.x, f0.y + g0.y, f0.z + g0.z, f0.w + g0.w,
                              f1.x + g1.x, f1.y + g1.y, f1.z + g1.z, f1.w + g1.w };
        const float wv[8] = { w0.x, w0.y, w0.z, w0.w, w1.x, w1.y, w1.z, w1.w };
        #pragma unroll
        for (int i = 0; i < 8; ++i) {
            const float h = fminf(fmaxf(accf[i] + bs[i], 0.f), 1.f);
            partial = fmaf(h, wv[i], partial);
        }
    }

    // 128 -> 1 reduction
    #pragma unroll
    for (int off = 16; off > 0; off >>= 1)
        partial += __shfl_down_sync(0xffffffffu, partial, off);
    if ((tid & 31) == 0) s_red[tid >> 5] = partial;
    __syncthreads();

    if (tid == 0) {
        const float x = s_red[0] + s_red[1] + s_red[2] + s_red[3] + __ldg(b_out);
        out[b] = 1.0f / (1.0f + expf(-x));
    }
}

extern "C" void kernel_launch(void* const* d_in, const int* in_sizes, int n_in,
                              void* d_out, int out_size)
{
    // metadata order: values, stm_feat, nstm_feat, batch_idx,
    //                 W_ft, b_ft, W_fft, b_fft, W_out, b_out, size
    const float* values    = (const float*)d_in[0];
    const int*   stm_feat  = (const int*)  d_in[1];
    const int*   nstm_feat = (const int*)  d_in[2];
    const float* W_ft      = (const float*)d_in[4];
    const float* b_ft      = (const float*)d_in[5];
    const float* W_fft     = (const float*)d_in[6];
    const float* b_fft     = (const float*)d_in[7];
    const float* W_out     = (const float*)d_in[8];
    const float* b_out     = (const float*)d_in[9];
    float*       out       = (float*)d_out;

    nnue_quant_kernel<<<N_FEAT, 256>>>(W_ft, W_fft);
    nnue_gather_kernel<<<BATCH, 128>>>(values, stm_feat, nstm_feat,
                                       b_ft, b_fft, W_out, b_out, out);
}